// round 6
// baseline (speedup 1.0000x reference)
#include <cuda_runtime.h>
#include <cuda_fp16.h>
#include <cstdint>

#define BATCH 8
#define TLEN  2048
#define CDIM  1024
#define HDIM  128
#define BT    (BATCH*TLEN)

__device__ __align__(16) __half g_q[BT*HDIM];
__device__ __align__(16) __half g_k[BT*HDIM];   // pre-scaled by 2^-5 * log2(e)
__device__ __align__(16) __half g_v[BT*HDIM];
__device__ __align__(16) __half g_wT[3*HDIM*CDIM];

// ------------------------- helpers -------------------------
__device__ __forceinline__ uint32_t smem_u32(const void* p) {
    uint32_t a;
    asm("{ .reg .u64 t; cvta.to.shared.u64 t, %1; cvt.u32.u64 %0, t; }"
        : "=r"(a) : "l"(p));
    return a;
}
__device__ __forceinline__ uint32_t pack_h2(float lo, float hi) {
    uint32_t d;
    asm("cvt.rn.f16x2.f32 %0, %1, %2;" : "=r"(d) : "f"(hi), "f"(lo));
    return d;
}
__device__ __forceinline__ void cp16(uint32_t dst, const void* src) {
    asm volatile("cp.async.cg.shared.global [%0], [%1], 16;" :: "r"(dst), "l"(src));
}
#define CP_COMMIT() asm volatile("cp.async.commit_group;" ::: "memory")
#define CP_WAIT0()  asm volatile("cp.async.wait_group 0;" ::: "memory")

__device__ __forceinline__ void ldsm4(uint32_t& r0, uint32_t& r1, uint32_t& r2,
                                      uint32_t& r3, uint32_t addr) {
    asm volatile("ldmatrix.sync.aligned.m8n8.x4.shared.b16 {%0,%1,%2,%3}, [%4];"
                 : "=r"(r0), "=r"(r1), "=r"(r2), "=r"(r3) : "r"(addr));
}
__device__ __forceinline__ void ldsm4t(uint32_t& r0, uint32_t& r1, uint32_t& r2,
                                       uint32_t& r3, uint32_t addr) {
    asm volatile("ldmatrix.sync.aligned.m8n8.x4.trans.shared.b16 {%0,%1,%2,%3}, [%4];"
                 : "=r"(r0), "=r"(r1), "=r"(r2), "=r"(r3) : "r"(addr));
}
__device__ __forceinline__ void mma16(float* d, const uint32_t* a, const uint32_t* b) {
    asm volatile(
        "mma.sync.aligned.m16n8k16.row.col.f32.f16.f16.f32 "
        "{%0,%1,%2,%3}, {%4,%5,%6,%7}, {%8,%9}, {%0,%1,%2,%3};"
        : "+f"(d[0]), "+f"(d[1]), "+f"(d[2]), "+f"(d[3])
        : "r"(a[0]), "r"(a[1]), "r"(a[2]), "r"(a[3]), "r"(b[0]), "r"(b[1]));
}
__device__ __forceinline__ float ex2(float x) {
    float e; asm("ex2.approx.f32 %0, %1;" : "=f"(e) : "f"(x)); return e;
}

// =====================================================================
// Kernel 0: W (CDIMxHDIM f32) -> W^T (HDIMxCDIM fp16)
// =====================================================================
__global__ __launch_bounds__(256) void wconv_kernel(
    const float* __restrict__ Wq, const float* __restrict__ Wk,
    const float* __restrict__ Wv)
{
    __shared__ float t[32][33];
    const int which = blockIdx.z;
    const float* W = (which == 0) ? Wq : (which == 1) ? Wk : Wv;
    const int c0 = blockIdx.x * 32, h0 = blockIdx.y * 32;
    const int tx = threadIdx.x, ty = threadIdx.y;
    #pragma unroll
    for (int i = 0; i < 32; i += 8)
        t[ty + i][tx] = W[(c0 + ty + i) * HDIM + h0 + tx];
    __syncthreads();
    #pragma unroll
    for (int i = 0; i < 32; i += 8)
        g_wT[(size_t)(which * HDIM + h0 + ty + i) * CDIM + c0 + tx] =
            __float2half_rn(t[tx][ty + i]);
}

// =====================================================================
// Kernel 1: QKV projection. BM=128, BN=128, BK=64, 256 thr.
// x: LDG.128->regs->cvt->STS fp16 (reg prefetch).  W^T: cp.async fp16.
// smem: W[2] 16K each @0, X[2] 16K each @32K.  One sync per iter.
// =====================================================================
#define QW_BUF 16384
#define QX_OFF 32768
#define QX_BUF 16384
#define QKV_SMEM 65536

__global__ __launch_bounds__(256) void qkv16_kernel(const float* __restrict__ x)
{
    extern __shared__ char sm[];
    const uint32_t smb = smem_u32(sm);
    const int bid = blockIdx.x;
    const int which = bid % 3;
    const int m0 = (bid / 3) * 128;
    const int tid = threadIdx.x, lane = tid & 31, wid = tid >> 5;
    const int wm = wid >> 1, wn = wid & 1;
    const int g = lane >> 2, tg = lane & 3;
    const __half* WT = g_wT + (size_t)which * HDIM * CDIM;
    __half* out = (which == 0) ? g_q : (which == 1) ? g_k : g_v;

    const int xrow = tid >> 1;              // 0..127
    const int xcb  = (tid & 1) * 4;         // chunk base 0 or 4
    const float* xsrc = x + (size_t)(m0 + xrow) * CDIM + (tid & 1) * 32;

    float acc[2][8][4];
    #pragma unroll
    for (int mt = 0; mt < 2; ++mt)
        #pragma unroll
        for (int nt = 0; nt < 8; ++nt)
            #pragma unroll
            for (int c = 0; c < 4; ++c) acc[mt][nt][c] = 0.f;

    float4 xr[8];
    auto ldgx = [&](int it) {
        const float4* p = (const float4*)(xsrc + it * 64);
        #pragma unroll
        for (int i = 0; i < 8; ++i) xr[i] = p[i];
    };
    auto issueW = [&](int it) {
        const uint32_t wb = smb + (it & 1) * QW_BUF;
        const int kc = it * 64;
        #pragma unroll
        for (int t = 0; t < 4; ++t) {       // 1024 chunks
            int idx = tid + t * 256;
            int r = idx >> 3, c = idx & 7;
            cp16(wb + r * 128 + ((c ^ (r & 7)) << 4),
                 WT + (size_t)r * CDIM + kc + c * 8);
        }
        CP_COMMIT();
    };

    issueW(0);
    ldgx(0);

    for (int it = 0; it < 16; ++it) {
        // STS x_it (fp16, swizzled)
        {
            char* xb = sm + QX_OFF + (it & 1) * QX_BUF + xrow * 128;
            const int r7 = xrow & 7;
            #pragma unroll
            for (int j = 0; j < 4; ++j) {
                uint4 u;
                u.x = pack_h2(xr[2*j].x,   xr[2*j].y);
                u.y = pack_h2(xr[2*j].z,   xr[2*j].w);
                u.z = pack_h2(xr[2*j+1].x, xr[2*j+1].y);
                u.w = pack_h2(xr[2*j+1].z, xr[2*j+1].w);
                *(uint4*)(xb + (((xcb + j) ^ r7) << 4)) = u;
            }
        }
        CP_WAIT0();                 // W_it landed
        __syncthreads();            // X_it visible; prev-iter readers done

        if (it + 1 < 16) { issueW(it + 1); ldgx(it + 1); }

        const uint32_t wb = smb + (it & 1) * QW_BUF;
        const uint32_t xb = smb + QX_OFF + (it & 1) * QX_BUF;

        #pragma unroll
        for (int q = 0; q < 4; ++q) {
            uint32_t bb[8][2];
            #pragma unroll
            for (int n2 = 0; n2 < 4; ++n2) {
                int row = wn * 64 + n2 * 16 + (lane & 7) + (((lane >> 4) & 1) << 3);
                int ch = q * 2 + ((lane >> 3) & 1);
                ldsm4(bb[2*n2][0], bb[2*n2][1], bb[2*n2+1][0], bb[2*n2+1][1],
                      wb + row * 128 + ((ch ^ (row & 7)) << 4));
            }
            uint32_t af[2][4];
            #pragma unroll
            for (int mt = 0; mt < 2; ++mt) {
                int row = wm * 32 + mt * 16 + (lane & 15);
                int ch = q * 2 + ((lane >> 4) & 1);
                ldsm4(af[mt][0], af[mt][1], af[mt][2], af[mt][3],
                      xb + row * 128 + ((ch ^ (row & 7)) << 4));
            }
            #pragma unroll
            for (int mt = 0; mt < 2; ++mt)
                #pragma unroll
                for (int nt = 0; nt < 8; ++nt)
                    mma16(acc[mt][nt], af[mt], bb[nt]);
        }
        __syncthreads();            // done reading bufs before next STS/cp overwrite
    }

    // epilogue (k pre-scaled by 2^-5 * log2 e)
    const float esc = (which == 1) ? 0.045084439f : 1.0f;
    #pragma unroll
    for (int mt = 0; mt < 2; ++mt) {
        #pragma unroll
        for (int nt = 0; nt < 8; ++nt) {
            const int r = m0 + wm * 32 + mt * 16 + g;
            const int col = wn * 64 + nt * 8 + 2 * tg;
            *(uint32_t*)(out + (size_t)r * HDIM + col) =
                pack_h2(acc[mt][nt][0] * esc, acc[mt][nt][1] * esc);
            *(uint32_t*)(out + (size_t)(r + 8) * HDIM + col) =
                pack_h2(acc[mt][nt][2] * esc, acc[mt][nt][3] * esc);
        }
    }
}

// =====================================================================
// Kernel 2: causal flash attention, fp16 mma, static-max softmax.
// 128 thr / 4 warps; warp = 16 q-rows x 64-key tile, P in registers.
// smem: K[2] 32K | V[2] 32K = 64K -> 3 CTAs/SM. Q staged via K-buf 1.
// grid 296, LPT pairing: SM gets units {s, 255-s}, cost sum == 33.
// =====================================================================
#define KB0 0
#define KB1 16384
#define VB0 32768
#define VB1 49152
#define KVBUF 16384
#define ATTN_SMEM 65536

__global__ __launch_bounds__(128, 3) void attn16_kernel(float* __restrict__ out)
{
    extern __shared__ char sm[];
    const uint32_t smb = smem_u32(sm);
    const int bid = blockIdx.x;
    if (bid >= 256) return;
    const int u = (bid < 148) ? bid : 403 - bid;
    const int qt = 31 - (u >> 3);
    const int b  = u & 7;
    const int q0 = qt * 64;
    const int ntiles = qt + 1;
    const int tid = threadIdx.x, lane = tid & 31, w = tid >> 5;
    const int g = lane >> 2, tg = lane & 3;

    // ---- prologue: Q (staged in K-buf 1) + K0 + V0 ----
    {
        const __half* gQ = g_q + ((size_t)b * TLEN + q0) * HDIM;
        const __half* gK = g_k + (size_t)b * TLEN * HDIM;
        const __half* gV = g_v + (size_t)b * TLEN * HDIM;
        #pragma unroll
        for (int t = 0; t < 8; ++t) {
            int idx = tid + t * 128;
            int r = idx >> 4, c = idx & 15;
            uint32_t so = r * 256 + ((c ^ (r & 7)) << 4);
            cp16(smb + KB1 + so, gQ + (size_t)r * HDIM + c * 8);
            cp16(smb + KB0 + so, gK + (size_t)r * HDIM + c * 8);
            cp16(smb + VB0 + so, gV + (size_t)r * HDIM + c * 8);
        }
        CP_COMMIT();
    }
    CP_WAIT0();
    __syncthreads();

    // ---- Q a-frags, register-resident ----
    uint32_t aq[8][4];
    {
        const int row = w * 16 + (lane & 15);
        #pragma unroll
        for (int q = 0; q < 8; ++q) {
            int ch = q * 2 + ((lane >> 4) & 1);
            ldsm4(aq[q][0], aq[q][1], aq[q][2], aq[q][3],
                  smb + KB1 + row * 256 + ((ch ^ (row & 7)) << 4));
        }
    }
    __syncthreads();    // K-buf 1 free for kt=1 prefetch

    float o[16][4];
    #pragma unroll
    for (int nt = 0; nt < 16; ++nt)
        #pragma unroll
        for (int c = 0; c < 4; ++c) o[nt][c] = 0.f;
    float lsum0 = 0.f, lsum1 = 0.f;

    for (int kt = 0; kt < ntiles; ++kt) {
        const int cur = kt & 1;
        if (kt) { CP_WAIT0(); __syncthreads(); }
        if (kt + 1 < ntiles) {
            const __half* gK = g_k + ((size_t)b * TLEN + (kt + 1) * 64) * HDIM;
            const __half* gV = g_v + ((size_t)b * TLEN + (kt + 1) * 64) * HDIM;
            const uint32_t dK = smb + KB0 + (cur ^ 1) * KVBUF;
            const uint32_t dV = smb + VB0 + (cur ^ 1) * KVBUF;
            #pragma unroll
            for (int t = 0; t < 8; ++t) {
                int idx = tid + t * 128;
                int r = idx >> 4, c = idx & 15;
                uint32_t so = r * 256 + ((c ^ (r & 7)) << 4);
                cp16(dK + so, gK + (size_t)r * HDIM + c * 8);
                cp16(dV + so, gV + (size_t)r * HDIM + c * 8);
            }
            CP_COMMIT();
        }

        // ---- S = Q K^T (K pre-scaled; s is already log2-domain) ----
        float s[8][4];
        #pragma unroll
        for (int nt = 0; nt < 8; ++nt)
            #pragma unroll
            for (int c = 0; c < 4; ++c) s[nt][c] = 0.f;

        const uint32_t kb = smb + KB0 + cur * KVBUF;
        #pragma unroll
        for (int q = 0; q < 8; ++q) {
            uint32_t bk[8][2];
            #pragma unroll
            for (int n2 = 0; n2 < 4; ++n2) {
                int row = n2 * 16 + (lane & 7) + (((lane >> 4) & 1) << 3);
                int ch = q * 2 + ((lane >> 3) & 1);
                ldsm4(bk[2*n2][0], bk[2*n2][1], bk[2*n2+1][0], bk[2*n2+1][1],
                      kb + row * 256 + ((ch ^ (row & 7)) << 4));
            }
            #pragma unroll
            for (int nt = 0; nt < 8; ++nt)
                mma16(s[nt], aq[q], bk[nt]);
        }

        // ---- softmax (static max 0), P a-frags in regs ----
        uint32_t ap[4][4];
        const int lrow0 = w * 16 + g, lrow1 = lrow0 + 8;
        if (kt == qt) {
            #pragma unroll
            for (int nt = 0; nt < 8; ++nt) {
                const int c0 = nt * 8 + 2 * tg, c1 = c0 + 1;
                float e0 = (c0 <= lrow0) ? ex2(s[nt][0]) : 0.f;
                float e1 = (c1 <= lrow0) ? ex2(s[nt][1]) : 0.f;
                float e2 = (c0 <= lrow1) ? ex2(s[nt][2]) : 0.f;
                float e3 = (c1 <= lrow1) ? ex2(s[nt][3]) : 0.f;
                lsum0 += e0 + e1; lsum1 += e2 + e3;
                ap[nt >> 1][((nt & 1) << 1) + 0] = pack_h2(e0, e1);
                ap[nt >> 1][((nt & 1) << 1) + 1] = pack_h2(e2, e3);
            }
        } else {
            #pragma unroll
            for (int nt = 0; nt < 8; ++nt) {
                float e0 = ex2(s[nt][0]);
                float e1 = ex2(s[nt][1]);
                float e2 = ex2(s[nt][2]);
                float e3 = ex2(s[nt][3]);
                lsum0 += e0 + e1; lsum1 += e2 + e3;
                ap[nt >> 1][((nt & 1) << 1) + 0] = pack_h2(e0, e1);
                ap[nt >> 1][((nt & 1) << 1) + 1] = pack_h2(e2, e3);
            }
        }

        // ---- O += P V ----
        const uint32_t vb = smb + VB0 + cur * KVBUF;
        #pragma unroll
        for (int ks = 0; ks < 4; ++ks) {
            const int key = ks * 16 + (lane & 7) + (((lane >> 3) & 1) << 3);
            #pragma unroll
            for (int n2 = 0; n2 < 8; ++n2) {
                uint32_t b0, b1, b2, b3;
                int ch = n2 * 2 + ((lane >> 4) & 1);
                ldsm4t(b0, b1, b2, b3,
                       vb + key * 256 + ((ch ^ (key & 7)) << 4));
                uint32_t bb0[2] = { b0, b1 }, bb1[2] = { b2, b3 };
                mma16(o[2*n2],     ap[ks], bb0);
                mma16(o[2*n2 + 1], ap[ks], bb1);
            }
        }
    }

    // ---- epilogue ----
    lsum0 += __shfl_xor_sync(0xffffffffu, lsum0, 1);
    lsum0 += __shfl_xor_sync(0xffffffffu, lsum0, 2);
    lsum1 += __shfl_xor_sync(0xffffffffu, lsum1, 1);
    lsum1 += __shfl_xor_sync(0xffffffffu, lsum1, 2);
    const float inv0 = 1.f / lsum0, inv1 = 1.f / lsum1;

    const size_t grow0 = (size_t)b * TLEN + q0 + w * 16 + g;
    const size_t grow1 = grow0 + 8;
    #pragma unroll
    for (int nt = 0; nt < 16; ++nt) {
        const int col = nt * 8 + 2 * tg;
        *(float2*)&out[grow0 * HDIM + col] = make_float2(o[nt][0] * inv0, o[nt][1] * inv0);
        *(float2*)&out[grow1 * HDIM + col] = make_float2(o[nt][2] * inv1, o[nt][3] * inv1);
    }
}

// ---------------------------------------------------------------------
extern "C" void kernel_launch(void* const* d_in, const int* in_sizes, int n_in,
                              void* d_out, int out_size)
{
    (void)in_sizes; (void)n_in; (void)out_size;
    const float* x  = (const float*)d_in[0];
    const float* Wq = (const float*)d_in[1];
    const float* Wk = (const float*)d_in[2];
    const float* Wv = (const float*)d_in[3];
    float* out = (float*)d_out;

    wconv_kernel<<<dim3(CDIM / 32, HDIM / 32, 3), dim3(32, 8)>>>(Wq, Wk, Wv);

    cudaFuncSetAttribute(qkv16_kernel,
                         cudaFuncAttributeMaxDynamicSharedMemorySize, QKV_SMEM);
    qkv16_kernel<<<(BT / 128) * 3, 256, QKV_SMEM>>>(x);

    cudaFuncSetAttribute(attn16_kernel,
                         cudaFuncAttributeMaxDynamicSharedMemorySize, ATTN_SMEM);
    attn16_kernel<<<296, 128, ATTN_SMEM>>>(out);
}

// round 7
// speedup vs baseline: 1.5251x; 1.5251x over previous
#include <cuda_runtime.h>
#include <cuda_fp16.h>
#include <cstdint>

#define BATCH 8
#define TLEN  2048
#define CDIM  1024
#define HDIM  128
#define BT    (BATCH*TLEN)

__device__ __align__(16) __half g_q[BT*HDIM];
__device__ __align__(16) __half g_k[BT*HDIM];   // pre-scaled by 2^-5 * log2(e)
__device__ __align__(16) __half g_v[BT*HDIM];
__device__ __align__(16) __half g_wT[3*HDIM*CDIM];

// ------------------------- helpers -------------------------
__device__ __forceinline__ uint32_t smem_u32(const void* p) {
    uint32_t a;
    asm("{ .reg .u64 t; cvta.to.shared.u64 t, %1; cvt.u32.u64 %0, t; }"
        : "=r"(a) : "l"(p));
    return a;
}
__device__ __forceinline__ uint32_t pack_h2(float lo, float hi) {
    uint32_t d;
    asm("cvt.rn.f16x2.f32 %0, %1, %2;" : "=r"(d) : "f"(hi), "f"(lo));
    return d;
}
__device__ __forceinline__ void cp16(uint32_t dst, const void* src) {
    asm volatile("cp.async.cg.shared.global [%0], [%1], 16;" :: "r"(dst), "l"(src));
}
#define CP_COMMIT() asm volatile("cp.async.commit_group;" ::: "memory")
#define CP_WAIT0()  asm volatile("cp.async.wait_group 0;" ::: "memory")
#define CP_WAIT1()  asm volatile("cp.async.wait_group 1;" ::: "memory")

__device__ __forceinline__ void ldsm4(uint32_t& r0, uint32_t& r1, uint32_t& r2,
                                      uint32_t& r3, uint32_t addr) {
    asm volatile("ldmatrix.sync.aligned.m8n8.x4.shared.b16 {%0,%1,%2,%3}, [%4];"
                 : "=r"(r0), "=r"(r1), "=r"(r2), "=r"(r3) : "r"(addr));
}
__device__ __forceinline__ void ldsm4t(uint32_t& r0, uint32_t& r1, uint32_t& r2,
                                       uint32_t& r3, uint32_t addr) {
    asm volatile("ldmatrix.sync.aligned.m8n8.x4.trans.shared.b16 {%0,%1,%2,%3}, [%4];"
                 : "=r"(r0), "=r"(r1), "=r"(r2), "=r"(r3) : "r"(addr));
}
__device__ __forceinline__ void mma16(float* d, const uint32_t* a, const uint32_t* b) {
    asm volatile(
        "mma.sync.aligned.m16n8k16.row.col.f32.f16.f16.f32 "
        "{%0,%1,%2,%3}, {%4,%5,%6,%7}, {%8,%9}, {%0,%1,%2,%3};"
        : "+f"(d[0]), "+f"(d[1]), "+f"(d[2]), "+f"(d[3])
        : "r"(a[0]), "r"(a[1]), "r"(a[2]), "r"(a[3]), "r"(b[0]), "r"(b[1]));
}
__device__ __forceinline__ float ex2(float x) {
    float e; asm("ex2.approx.f32 %0, %1;" : "=f"(e) : "f"(x)); return e;
}

// =====================================================================
// Kernel 0: W (CDIMxHDIM f32) -> W^T (HDIMxCDIM fp16), 3 matrices.
// =====================================================================
__global__ __launch_bounds__(256) void wconv_kernel(
    const float* __restrict__ Wq, const float* __restrict__ Wk,
    const float* __restrict__ Wv)
{
    __shared__ float t[32][33];
    const int which = blockIdx.z;
    const float* W = (which == 0) ? Wq : (which == 1) ? Wk : Wv;
    const int c0 = blockIdx.x * 32, h0 = blockIdx.y * 32;
    const int tx = threadIdx.x, ty = threadIdx.y;   // 32 x 8
    #pragma unroll
    for (int i = 0; i < 32; i += 8)
        t[ty + i][tx] = W[(c0 + ty + i) * HDIM + h0 + tx];
    __syncthreads();
    #pragma unroll
    for (int i = 0; i < 32; i += 8)
        g_wT[(size_t)(which * HDIM + h0 + ty + i) * CDIM + c0 + tx] =
            __float2half_rn(t[tx][ty + i]);
}

// =====================================================================
// Kernel 1: QKV projection, fp16 mma, cp.async double-buffered.
// BM=128, BN=128(full H), BK=64. 256 thr, 8 warps = 4(wm) x 2(wn).
// smem: X f32 [2][128 rows x 256B swizzled], W^T fp16 [2][128 rows x 128B]
// (exact R5 structure — known good)
// =====================================================================
#define QX_BUF 32768
#define QW_OFF 65536
#define QW_BUF 16384
#define QKV_SMEM 98304

__global__ __launch_bounds__(256, 2) void qkv16_kernel(const float* __restrict__ x)
{
    extern __shared__ char sm[];
    const uint32_t smb = smem_u32(sm);
    const int bid = blockIdx.x;
    const int which = bid % 3;
    const int m0 = (bid / 3) * 128;
    const int tid = threadIdx.x, lane = tid & 31, wid = tid >> 5;
    const int wm = wid >> 1, wn = wid & 1;
    const int g = lane >> 2, tg = lane & 3;
    const __half* WT = g_wT + (size_t)which * HDIM * CDIM;
    __half* out = (which == 0) ? g_q : (which == 1) ? g_k : g_v;

    float acc[2][8][4];
    #pragma unroll
    for (int mt = 0; mt < 2; ++mt)
        #pragma unroll
        for (int nt = 0; nt < 8; ++nt)
            #pragma unroll
            for (int c = 0; c < 4; ++c) acc[mt][nt][c] = 0.f;

    auto issue = [&](int it) {
        const int kc = it * 64, buf = it & 1;
        const uint32_t xb = smb + buf * QX_BUF;
        #pragma unroll
        for (int t = 0; t < 8; ++t) {           // 2048 16B chunks of f32 x
            int idx = tid + t * 256;
            int r = idx >> 4, c = idx & 15;
            cp16(xb + r * 256 + ((c ^ (r & 7)) << 4),
                 x + (size_t)(m0 + r) * CDIM + kc + c * 4);
        }
        const uint32_t wb = smb + QW_OFF + buf * QW_BUF;
        #pragma unroll
        for (int t = 0; t < 4; ++t) {           // 1024 16B chunks of fp16 W^T
            int idx = tid + t * 256;
            int r = idx >> 3, c = idx & 7;
            cp16(wb + r * 128 + ((c ^ (r & 7)) << 4),
                 WT + (size_t)r * CDIM + kc + c * 8);
        }
        CP_COMMIT();
    };

    issue(0);
    for (int it = 0; it < 16; ++it) {
        const int buf = it & 1;
        if (it) __syncthreads();                 // all warps done with buf
        if (it + 1 < 16) { issue(it + 1); CP_WAIT1(); } else CP_WAIT0();
        __syncthreads();

        const uint32_t wb = smb + QW_OFF + buf * QW_BUF;
        const char* xb = sm + buf * QX_BUF;

        #pragma unroll
        for (int q = 0; q < 4; ++q) {            // k16 chunks within BK=64
            // B frags (W^T) via ldmatrix: 8 ntiles
            uint32_t bb[8][2];
            #pragma unroll
            for (int n2 = 0; n2 < 4; ++n2) {
                int row = wn * 64 + n2 * 16 + (lane & 7) + (((lane >> 4) & 1) << 3);
                int ch = q * 2 + ((lane >> 3) & 1);
                ldsm4(bb[2*n2][0], bb[2*n2][1], bb[2*n2+1][0], bb[2*n2+1][1],
                      wb + row * 128 + ((ch ^ (row & 7)) << 4));
            }
            // A frags from f32 x -> half2
            uint32_t af[2][4];
            #pragma unroll
            for (int mt = 0; mt < 2; ++mt) {
                const int r0 = wm * 32 + mt * 16 + g, r1 = r0 + 8;
                const int ch0 = q * 4 + (tg >> 1), ch1 = ch0 + 2;
                const int ib = (tg & 1) * 8;
                float2 v00 = *(const float2*)(xb + r0 * 256 + ((ch0 ^ (r0 & 7)) << 4) + ib);
                float2 v10 = *(const float2*)(xb + r1 * 256 + ((ch0 ^ (r1 & 7)) << 4) + ib);
                float2 v01 = *(const float2*)(xb + r0 * 256 + ((ch1 ^ (r0 & 7)) << 4) + ib);
                float2 v11 = *(const float2*)(xb + r1 * 256 + ((ch1 ^ (r1 & 7)) << 4) + ib);
                af[mt][0] = pack_h2(v00.x, v00.y);
                af[mt][1] = pack_h2(v10.x, v10.y);
                af[mt][2] = pack_h2(v01.x, v01.y);
                af[mt][3] = pack_h2(v11.x, v11.y);
            }
            #pragma unroll
            for (int mt = 0; mt < 2; ++mt)
                #pragma unroll
                for (int nt = 0; nt < 8; ++nt)
                    mma16(acc[mt][nt], af[mt], bb[nt]);
        }
    }

    // epilogue -> fp16 (K pre-scaled by 2^-5 * log2 e)
    const float esc = (which == 1) ? 0.045084439f : 1.0f;
    #pragma unroll
    for (int mt = 0; mt < 2; ++mt) {
        #pragma unroll
        for (int nt = 0; nt < 8; ++nt) {
            const int r = m0 + wm * 32 + mt * 16 + g;
            const int col = wn * 64 + nt * 8 + 2 * tg;
            *(uint32_t*)(out + (size_t)r * HDIM + col) =
                pack_h2(acc[mt][nt][0] * esc, acc[mt][nt][1] * esc);
            *(uint32_t*)(out + (size_t)(r + 8) * HDIM + col) =
                pack_h2(acc[mt][nt][2] * esc, acc[mt][nt][3] * esc);
        }
    }
}

// =====================================================================
// Kernel 2: causal flash attention, fp16 mma, static-max softmax.
// 128 thr / 4 warps; warp = 16 q-rows x full 64-key tile (P in regs).
// smem: Q 16K | K[2] 32K | V[2] 32K = 80K -> 2 CTAs/SM.
// LPT schedule: u = bid<148 ? bid : 403-bid  (wave1 heavy, wave2 light)
// =====================================================================
#define AK_OFF 16384
#define AV_OFF 49152
#define ATTN_SMEM 81920
#define KVBUF 16384

__global__ __launch_bounds__(128, 2) void attn16_kernel(float* __restrict__ out)
{
    extern __shared__ char sm[];
    const uint32_t smb = smem_u32(sm);
    const int bid = blockIdx.x;
    const int u = (bid < 148) ? bid : 403 - bid;   // bijection on [0,256)
    const int qt = 31 - (u >> 3);
    const int b  = u & 7;
    const int q0 = qt * 64;
    const int ntiles = qt + 1;
    const int tid = threadIdx.x, lane = tid & 31, w = tid >> 5;
    const int g = lane >> 2, tg = lane & 3;

    // ---- prologue: Q + K0 + V0 via cp.async ----
    {
        const __half* gQ = g_q + ((size_t)b * TLEN + q0) * HDIM;
        const __half* gK = g_k + (size_t)b * TLEN * HDIM;
        const __half* gV = g_v + (size_t)b * TLEN * HDIM;
        #pragma unroll
        for (int t = 0; t < 8; ++t) {           // 1024 chunks each
            int idx = tid + t * 128;
            int r = idx >> 4, c = idx & 15;
            uint32_t so = r * 256 + ((c ^ (r & 7)) << 4);
            cp16(smb + so,          gQ + (size_t)r * HDIM + c * 8);
            cp16(smb + AK_OFF + so, gK + (size_t)r * HDIM + c * 8);
            cp16(smb + AV_OFF + so, gV + (size_t)r * HDIM + c * 8);
        }
        CP_COMMIT();
    }
    CP_WAIT0();
    __syncthreads();

    // ---- Q a-frags, register-resident for all tiles ----
    uint32_t aq[8][4];
    {
        const int row = w * 16 + (lane & 15);
        #pragma unroll
        for (int q = 0; q < 8; ++q) {
            int ch = q * 2 + ((lane >> 4) & 1);
            ldsm4(aq[q][0], aq[q][1], aq[q][2], aq[q][3],
                  smb + row * 256 + ((ch ^ (row & 7)) << 4));
        }
    }

    float o[16][4];
    #pragma unroll
    for (int nt = 0; nt < 16; ++nt)
        #pragma unroll
        for (int c = 0; c < 4; ++c) o[nt][c] = 0.f;
    float lsum0 = 0.f, lsum1 = 0.f;

    for (int kt = 0; kt < ntiles; ++kt) {
        const int cur = kt & 1;
        if (kt) { CP_WAIT0(); __syncthreads(); }
        // prefetch next K/V into other buffer (overlaps compute of this tile)
        if (kt + 1 < ntiles) {
            const __half* gK = g_k + ((size_t)b * TLEN + (kt + 1) * 64) * HDIM;
            const __half* gV = g_v + ((size_t)b * TLEN + (kt + 1) * 64) * HDIM;
            const uint32_t dK = smb + AK_OFF + (cur ^ 1) * KVBUF;
            const uint32_t dV = smb + AV_OFF + (cur ^ 1) * KVBUF;
            #pragma unroll
            for (int t = 0; t < 8; ++t) {
                int idx = tid + t * 128;
                int r = idx >> 4, c = idx & 15;
                uint32_t so = r * 256 + ((c ^ (r & 7)) << 4);
                cp16(dK + so, gK + (size_t)r * HDIM + c * 8);
                cp16(dV + so, gV + (size_t)r * HDIM + c * 8);
            }
            CP_COMMIT();
        }

        // ---- S = Q K^T : 16 rows x 64 keys (K pre-scaled; log2 domain) ----
        float s[8][4];
        #pragma unroll
        for (int nt = 0; nt < 8; ++nt)
            #pragma unroll
            for (int c = 0; c < 4; ++c) s[nt][c] = 0.f;

        const uint32_t kb = smb + AK_OFF + cur * KVBUF;
        #pragma unroll
        for (int q = 0; q < 8; ++q) {
            uint32_t bk[8][2];
            #pragma unroll
            for (int n2 = 0; n2 < 4; ++n2) {
                int row = n2 * 16 + (lane & 7) + (((lane >> 4) & 1) << 3);
                int ch = q * 2 + ((lane >> 3) & 1);
                ldsm4(bk[2*n2][0], bk[2*n2][1], bk[2*n2+1][0], bk[2*n2+1][1],
                      kb + row * 256 + ((ch ^ (row & 7)) << 4));
            }
            #pragma unroll
            for (int nt = 0; nt < 8; ++nt)
                mma16(s[nt], aq[q], bk[nt]);
        }

        // ---- softmax (static max = 0); P a-frags in registers ----
        uint32_t ap[4][4];
        const int lrow0 = w * 16 + g, lrow1 = lrow0 + 8;
        if (kt == qt) {   // diagonal tile: causal mask
            #pragma unroll
            for (int nt = 0; nt < 8; ++nt) {
                const int c0 = nt * 8 + 2 * tg, c1 = c0 + 1;
                float e0 = (c0 <= lrow0) ? ex2(s[nt][0]) : 0.f;
                float e1 = (c1 <= lrow0) ? ex2(s[nt][1]) : 0.f;
                float e2 = (c0 <= lrow1) ? ex2(s[nt][2]) : 0.f;
                float e3 = (c1 <= lrow1) ? ex2(s[nt][3]) : 0.f;
                lsum0 += e0 + e1; lsum1 += e2 + e3;
                ap[nt >> 1][((nt & 1) << 1) + 0] = pack_h2(e0, e1);
                ap[nt >> 1][((nt & 1) << 1) + 1] = pack_h2(e2, e3);
            }
        } else {
            #pragma unroll
            for (int nt = 0; nt < 8; ++nt) {
                float e0 = ex2(s[nt][0]);
                float e1 = ex2(s[nt][1]);
                float e2 = ex2(s[nt][2]);
                float e3 = ex2(s[nt][3]);
                lsum0 += e0 + e1; lsum1 += e2 + e3;
                ap[nt >> 1][((nt & 1) << 1) + 0] = pack_h2(e0, e1);
                ap[nt >> 1][((nt & 1) << 1) + 1] = pack_h2(e2, e3);
            }
        }

        // ---- O += P V ----
        const uint32_t vb = smb + AV_OFF + cur * KVBUF;
        #pragma unroll
        for (int ks = 0; ks < 4; ++ks) {
            const int key = ks * 16 + (lane & 7) + (((lane >> 3) & 1) << 3);
            #pragma unroll
            for (int n2 = 0; n2 < 8; ++n2) {
                uint32_t b0, b1, b2, b3;
                int ch = n2 * 2 + ((lane >> 4) & 1);
                ldsm4t(b0, b1, b2, b3,
                       vb + key * 256 + ((ch ^ (key & 7)) << 4));
                uint32_t bb0[2] = { b0, b1 }, bb1[2] = { b2, b3 };
                mma16(o[2*n2],     ap[ks], bb0);
                mma16(o[2*n2 + 1], ap[ks], bb1);
            }
        }
    }

    // ---- epilogue: reduce l over tg lanes, write O/l ----
    lsum0 += __shfl_xor_sync(0xffffffffu, lsum0, 1);
    lsum0 += __shfl_xor_sync(0xffffffffu, lsum0, 2);
    lsum1 += __shfl_xor_sync(0xffffffffu, lsum1, 1);
    lsum1 += __shfl_xor_sync(0xffffffffu, lsum1, 2);
    const float inv0 = 1.f / lsum0, inv1 = 1.f / lsum1;

    const size_t grow0 = (size_t)b * TLEN + q0 + w * 16 + g;
    const size_t grow1 = grow0 + 8;
    #pragma unroll
    for (int nt = 0; nt < 16; ++nt) {
        const int col = nt * 8 + 2 * tg;
        *(float2*)&out[grow0 * HDIM + col] = make_float2(o[nt][0] * inv0, o[nt][1] * inv0);
        *(float2*)&out[grow1 * HDIM + col] = make_float2(o[nt][2] * inv1, o[nt][3] * inv1);
    }
}

// ---------------------------------------------------------------------
extern "C" void kernel_launch(void* const* d_in, const int* in_sizes, int n_in,
                              void* d_out, int out_size)
{
    (void)in_sizes; (void)n_in; (void)out_size;
    const float* x  = (const float*)d_in[0];
    const float* Wq = (const float*)d_in[1];
    const float* Wk = (const float*)d_in[2];
    const float* Wv = (const float*)d_in[3];
    float* out = (float*)d_out;

    wconv_kernel<<<dim3(CDIM / 32, HDIM / 32, 3), dim3(32, 8)>>>(Wq, Wk, Wv);

    cudaFuncSetAttribute(qkv16_kernel,
                         cudaFuncAttributeMaxDynamicSharedMemorySize, QKV_SMEM);
    qkv16_kernel<<<(BT / 128) * 3, 256, QKV_SMEM>>>(x);

    cudaFuncSetAttribute(attn16_kernel,
                         cudaFuncAttributeMaxDynamicSharedMemorySize, ATTN_SMEM);
    attn16_kernel<<<256, 128, ATTN_SMEM>>>(out);
}

// round 8
// speedup vs baseline: 1.5585x; 1.0219x over previous
#include <cuda_runtime.h>
#include <cuda_fp16.h>
#include <cstdint>

#define BATCH 8
#define TLEN  2048
#define CDIM  1024
#define HDIM  128
#define BT    (BATCH*TLEN)

__device__ __align__(16) __half g_q[BT*HDIM];
__device__ __align__(16) __half g_k[BT*HDIM];   // pre-scaled by 2^-5 * log2(e)
__device__ __align__(16) __half g_v[BT*HDIM];
__device__ __align__(16) __half g_wT[3*HDIM*CDIM];
__device__ __align__(16) __half g_x16[BT*CDIM];

// ------------------------- helpers -------------------------
__device__ __forceinline__ uint32_t smem_u32(const void* p) {
    uint32_t a;
    asm("{ .reg .u64 t; cvta.to.shared.u64 t, %1; cvt.u32.u64 %0, t; }"
        : "=r"(a) : "l"(p));
    return a;
}
__device__ __forceinline__ uint32_t pack_h2(float lo, float hi) {
    uint32_t d;
    asm("cvt.rn.f16x2.f32 %0, %1, %2;" : "=r"(d) : "f"(hi), "f"(lo));
    return d;
}
__device__ __forceinline__ void cp16(uint32_t dst, const void* src) {
    asm volatile("cp.async.cg.shared.global [%0], [%1], 16;" :: "r"(dst), "l"(src));
}
#define CP_COMMIT() asm volatile("cp.async.commit_group;" ::: "memory")
#define CP_WAIT0()  asm volatile("cp.async.wait_group 0;" ::: "memory")
#define CP_WAIT1()  asm volatile("cp.async.wait_group 1;" ::: "memory")

__device__ __forceinline__ void ldsm4(uint32_t& r0, uint32_t& r1, uint32_t& r2,
                                      uint32_t& r3, uint32_t addr) {
    asm volatile("ldmatrix.sync.aligned.m8n8.x4.shared.b16 {%0,%1,%2,%3}, [%4];"
                 : "=r"(r0), "=r"(r1), "=r"(r2), "=r"(r3) : "r"(addr));
}
__device__ __forceinline__ void ldsm4t(uint32_t& r0, uint32_t& r1, uint32_t& r2,
                                       uint32_t& r3, uint32_t addr) {
    asm volatile("ldmatrix.sync.aligned.m8n8.x4.trans.shared.b16 {%0,%1,%2,%3}, [%4];"
                 : "=r"(r0), "=r"(r1), "=r"(r2), "=r"(r3) : "r"(addr));
}
__device__ __forceinline__ void mma16(float* d, const uint32_t* a, const uint32_t* b) {
    asm volatile(
        "mma.sync.aligned.m16n8k16.row.col.f32.f16.f16.f32 "
        "{%0,%1,%2,%3}, {%4,%5,%6,%7}, {%8,%9}, {%0,%1,%2,%3};"
        : "+f"(d[0]), "+f"(d[1]), "+f"(d[2]), "+f"(d[3])
        : "r"(a[0]), "r"(a[1]), "r"(a[2]), "r"(a[3]), "r"(b[0]), "r"(b[1]));
}
__device__ __forceinline__ float ex2(float x) {
    float e; asm("ex2.approx.f32 %0, %1;" : "=f"(e) : "f"(x)); return e;
}

// =====================================================================
// Kernel 0a: x (f32) -> x16 (fp16), pure bandwidth.
// =====================================================================
__global__ __launch_bounds__(256) void xconv_kernel(const float* __restrict__ x)
{
    const size_t i = ((size_t)blockIdx.x * 256 + threadIdx.x) * 8;
    float4 a = *(const float4*)(x + i);
    float4 b = *(const float4*)(x + i + 4);
    uint4 u;
    u.x = pack_h2(a.x, a.y); u.y = pack_h2(a.z, a.w);
    u.z = pack_h2(b.x, b.y); u.w = pack_h2(b.z, b.w);
    *(uint4*)(g_x16 + i) = u;
}

// =====================================================================
// Kernel 0b: W (CDIMxHDIM f32) -> W^T (HDIMxCDIM fp16), 3 matrices.
// =====================================================================
__global__ __launch_bounds__(256) void wconv_kernel(
    const float* __restrict__ Wq, const float* __restrict__ Wk,
    const float* __restrict__ Wv)
{
    __shared__ float t[32][33];
    const int which = blockIdx.z;
    const float* W = (which == 0) ? Wq : (which == 1) ? Wk : Wv;
    const int c0 = blockIdx.x * 32, h0 = blockIdx.y * 32;
    const int tx = threadIdx.x, ty = threadIdx.y;   // 32 x 8
    #pragma unroll
    for (int i = 0; i < 32; i += 8)
        t[ty + i][tx] = W[(c0 + ty + i) * HDIM + h0 + tx];
    __syncthreads();
    #pragma unroll
    for (int i = 0; i < 32; i += 8)
        g_wT[(size_t)(which * HDIM + h0 + ty + i) * CDIM + c0 + tx] =
            __float2half_rn(t[tx][ty + i]);
}

// =====================================================================
// Kernel 1: QKV projection, pure fp16 mma, cp.async double-buffered.
// BM=128, BN=128(full H), BK=64. 256 thr, 8 warps = 4(wm) x 2(wn).
// smem: X16[2] 16K each @0, W^T[2] 16K each @32K. Total 64K.
// =====================================================================
#define QX_BUF 16384
#define QW_OFF 32768
#define QW_BUF 16384
#define QKV_SMEM 65536

__global__ __launch_bounds__(256, 2) void qkv16_kernel()
{
    extern __shared__ char sm[];
    const uint32_t smb = smem_u32(sm);
    const int bid = blockIdx.x;
    const int which = bid % 3;
    const int m0 = (bid / 3) * 128;
    const int tid = threadIdx.x, lane = tid & 31, wid = tid >> 5;
    const int wm = wid >> 1, wn = wid & 1;
    const int g = lane >> 2, tg = lane & 3;
    const __half* WT = g_wT + (size_t)which * HDIM * CDIM;
    const __half* GX = g_x16;
    __half* out = (which == 0) ? g_q : (which == 1) ? g_k : g_v;

    float acc[2][8][4];
    #pragma unroll
    for (int mt = 0; mt < 2; ++mt)
        #pragma unroll
        for (int nt = 0; nt < 8; ++nt)
            #pragma unroll
            for (int c = 0; c < 4; ++c) acc[mt][nt][c] = 0.f;

    auto issue = [&](int it) {
        const int kc = it * 64, buf = it & 1;
        const uint32_t xb = smb + buf * QX_BUF;
        #pragma unroll
        for (int t = 0; t < 4; ++t) {           // 1024 chunks of fp16 x
            int idx = tid + t * 256;
            int r = idx >> 3, c = idx & 7;
            cp16(xb + r * 128 + ((c ^ (r & 7)) << 4),
                 GX + (size_t)(m0 + r) * CDIM + kc + c * 8);
        }
        const uint32_t wb = smb + QW_OFF + buf * QW_BUF;
        #pragma unroll
        for (int t = 0; t < 4; ++t) {           // 1024 chunks of fp16 W^T
            int idx = tid + t * 256;
            int r = idx >> 3, c = idx & 7;
            cp16(wb + r * 128 + ((c ^ (r & 7)) << 4),
                 WT + (size_t)r * CDIM + kc + c * 8);
        }
        CP_COMMIT();
    };

    issue(0);
    for (int it = 0; it < 16; ++it) {
        const int buf = it & 1;
        if (it) __syncthreads();                 // all warps done with buf
        if (it + 1 < 16) { issue(it + 1); CP_WAIT1(); } else CP_WAIT0();
        __syncthreads();

        const uint32_t wb = smb + QW_OFF + buf * QW_BUF;
        const uint32_t xb = smb + buf * QX_BUF;

        #pragma unroll
        for (int q = 0; q < 4; ++q) {            // k16 chunks within BK=64
            // B frags (W^T) via ldmatrix
            uint32_t bb[8][2];
            #pragma unroll
            for (int n2 = 0; n2 < 4; ++n2) {
                int row = wn * 64 + n2 * 16 + (lane & 7) + (((lane >> 4) & 1) << 3);
                int ch = q * 2 + ((lane >> 3) & 1);
                ldsm4(bb[2*n2][0], bb[2*n2][1], bb[2*n2+1][0], bb[2*n2+1][1],
                      wb + row * 128 + ((ch ^ (row & 7)) << 4));
            }
            // A frags (x16) via ldmatrix — same mapping as attn aq (proven)
            uint32_t af[2][4];
            #pragma unroll
            for (int mt = 0; mt < 2; ++mt) {
                int row = wm * 32 + mt * 16 + (lane & 15);
                int ch = q * 2 + ((lane >> 4) & 1);
                ldsm4(af[mt][0], af[mt][1], af[mt][2], af[mt][3],
                      xb + row * 128 + ((ch ^ (row & 7)) << 4));
            }
            #pragma unroll
            for (int mt = 0; mt < 2; ++mt)
                #pragma unroll
                for (int nt = 0; nt < 8; ++nt)
                    mma16(acc[mt][nt], af[mt], bb[nt]);
        }
    }

    // epilogue -> fp16 (K pre-scaled by 2^-5 * log2 e)
    const float esc = (which == 1) ? 0.045084439f : 1.0f;
    #pragma unroll
    for (int mt = 0; mt < 2; ++mt) {
        #pragma unroll
        for (int nt = 0; nt < 8; ++nt) {
            const int r = m0 + wm * 32 + mt * 16 + g;
            const int col = wn * 64 + nt * 8 + 2 * tg;
            *(uint32_t*)(out + (size_t)r * HDIM + col) =
                pack_h2(acc[mt][nt][0] * esc, acc[mt][nt][1] * esc);
            *(uint32_t*)(out + (size_t)(r + 8) * HDIM + col) =
                pack_h2(acc[mt][nt][2] * esc, acc[mt][nt][3] * esc);
        }
    }
}

// =====================================================================
// Kernel 2: causal flash attention — BYTE-IDENTICAL to R7 (known good).
// 128 thr / 4 warps; warp = 16 q-rows x full 64-key tile (P in regs).
// smem: Q 16K | K[2] 32K | V[2] 32K = 80K -> 2 CTAs/SM.
// LPT schedule: u = bid<148 ? bid : 403-bid
// =====================================================================
#define AK_OFF 16384
#define AV_OFF 49152
#define ATTN_SMEM 81920
#define KVBUF 16384

__global__ __launch_bounds__(128, 2) void attn16_kernel(float* __restrict__ out)
{
    extern __shared__ char sm[];
    const uint32_t smb = smem_u32(sm);
    const int bid = blockIdx.x;
    const int u = (bid < 148) ? bid : 403 - bid;   // bijection on [0,256)
    const int qt = 31 - (u >> 3);
    const int b  = u & 7;
    const int q0 = qt * 64;
    const int ntiles = qt + 1;
    const int tid = threadIdx.x, lane = tid & 31, w = tid >> 5;
    const int g = lane >> 2, tg = lane & 3;

    // ---- prologue: Q + K0 + V0 via cp.async ----
    {
        const __half* gQ = g_q + ((size_t)b * TLEN + q0) * HDIM;
        const __half* gK = g_k + (size_t)b * TLEN * HDIM;
        const __half* gV = g_v + (size_t)b * TLEN * HDIM;
        #pragma unroll
        for (int t = 0; t < 8; ++t) {           // 1024 chunks each
            int idx = tid + t * 128;
            int r = idx >> 4, c = idx & 15;
            uint32_t so = r * 256 + ((c ^ (r & 7)) << 4);
            cp16(smb + so,          gQ + (size_t)r * HDIM + c * 8);
            cp16(smb + AK_OFF + so, gK + (size_t)r * HDIM + c * 8);
            cp16(smb + AV_OFF + so, gV + (size_t)r * HDIM + c * 8);
        }
        CP_COMMIT();
    }
    CP_WAIT0();
    __syncthreads();

    // ---- Q a-frags, register-resident for all tiles ----
    uint32_t aq[8][4];
    {
        const int row = w * 16 + (lane & 15);
        #pragma unroll
        for (int q = 0; q < 8; ++q) {
            int ch = q * 2 + ((lane >> 4) & 1);
            ldsm4(aq[q][0], aq[q][1], aq[q][2], aq[q][3],
                  smb + row * 256 + ((ch ^ (row & 7)) << 4));
        }
    }

    float o[16][4];
    #pragma unroll
    for (int nt = 0; nt < 16; ++nt)
        #pragma unroll
        for (int c = 0; c < 4; ++c) o[nt][c] = 0.f;
    float lsum0 = 0.f, lsum1 = 0.f;

    for (int kt = 0; kt < ntiles; ++kt) {
        const int cur = kt & 1;
        if (kt) { CP_WAIT0(); __syncthreads(); }
        if (kt + 1 < ntiles) {
            const __half* gK = g_k + ((size_t)b * TLEN + (kt + 1) * 64) * HDIM;
            const __half* gV = g_v + ((size_t)b * TLEN + (kt + 1) * 64) * HDIM;
            const uint32_t dK = smb + AK_OFF + (cur ^ 1) * KVBUF;
            const uint32_t dV = smb + AV_OFF + (cur ^ 1) * KVBUF;
            #pragma unroll
            for (int t = 0; t < 8; ++t) {
                int idx = tid + t * 128;
                int r = idx >> 4, c = idx & 15;
                uint32_t so = r * 256 + ((c ^ (r & 7)) << 4);
                cp16(dK + so, gK + (size_t)r * HDIM + c * 8);
                cp16(dV + so, gV + (size_t)r * HDIM + c * 8);
            }
            CP_COMMIT();
        }

        // ---- S = Q K^T (K pre-scaled; log2 domain) ----
        float s[8][4];
        #pragma unroll
        for (int nt = 0; nt < 8; ++nt)
            #pragma unroll
            for (int c = 0; c < 4; ++c) s[nt][c] = 0.f;

        const uint32_t kb = smb + AK_OFF + cur * KVBUF;
        #pragma unroll
        for (int q = 0; q < 8; ++q) {
            uint32_t bk[8][2];
            #pragma unroll
            for (int n2 = 0; n2 < 4; ++n2) {
                int row = n2 * 16 + (lane & 7) + (((lane >> 4) & 1) << 3);
                int ch = q * 2 + ((lane >> 3) & 1);
                ldsm4(bk[2*n2][0], bk[2*n2][1], bk[2*n2+1][0], bk[2*n2+1][1],
                      kb + row * 256 + ((ch ^ (row & 7)) << 4));
            }
            #pragma unroll
            for (int nt = 0; nt < 8; ++nt)
                mma16(s[nt], aq[q], bk[nt]);
        }

        // ---- softmax (static max = 0); P a-frags in registers ----
        uint32_t ap[4][4];
        const int lrow0 = w * 16 + g, lrow1 = lrow0 + 8;
        if (kt == qt) {
            #pragma unroll
            for (int nt = 0; nt < 8; ++nt) {
                const int c0 = nt * 8 + 2 * tg, c1 = c0 + 1;
                float e0 = (c0 <= lrow0) ? ex2(s[nt][0]) : 0.f;
                float e1 = (c1 <= lrow0) ? ex2(s[nt][1]) : 0.f;
                float e2 = (c0 <= lrow1) ? ex2(s[nt][2]) : 0.f;
                float e3 = (c1 <= lrow1) ? ex2(s[nt][3]) : 0.f;
                lsum0 += e0 + e1; lsum1 += e2 + e3;
                ap[nt >> 1][((nt & 1) << 1) + 0] = pack_h2(e0, e1);
                ap[nt >> 1][((nt & 1) << 1) + 1] = pack_h2(e2, e3);
            }
        } else {
            #pragma unroll
            for (int nt = 0; nt < 8; ++nt) {
                float e0 = ex2(s[nt][0]);
                float e1 = ex2(s[nt][1]);
                float e2 = ex2(s[nt][2]);
                float e3 = ex2(s[nt][3]);
                lsum0 += e0 + e1; lsum1 += e2 + e3;
                ap[nt >> 1][((nt & 1) << 1) + 0] = pack_h2(e0, e1);
                ap[nt >> 1][((nt & 1) << 1) + 1] = pack_h2(e2, e3);
            }
        }

        // ---- O += P V ----
        const uint32_t vb = smb + AV_OFF + cur * KVBUF;
        #pragma unroll
        for (int ks = 0; ks < 4; ++ks) {
            const int key = ks * 16 + (lane & 7) + (((lane >> 3) & 1) << 3);
            #pragma unroll
            for (int n2 = 0; n2 < 8; ++n2) {
                uint32_t b0, b1, b2, b3;
                int ch = n2 * 2 + ((lane >> 4) & 1);
                ldsm4t(b0, b1, b2, b3,
                       vb + key * 256 + ((ch ^ (key & 7)) << 4));
                uint32_t bb0[2] = { b0, b1 }, bb1[2] = { b2, b3 };
                mma16(o[2*n2],     ap[ks], bb0);
                mma16(o[2*n2 + 1], ap[ks], bb1);
            }
        }
    }

    // ---- epilogue: reduce l over tg lanes, write O/l ----
    lsum0 += __shfl_xor_sync(0xffffffffu, lsum0, 1);
    lsum0 += __shfl_xor_sync(0xffffffffu, lsum0, 2);
    lsum1 += __shfl_xor_sync(0xffffffffu, lsum1, 1);
    lsum1 += __shfl_xor_sync(0xffffffffu, lsum1, 2);
    const float inv0 = 1.f / lsum0, inv1 = 1.f / lsum1;

    const size_t grow0 = (size_t)b * TLEN + q0 + w * 16 + g;
    const size_t grow1 = grow0 + 8;
    #pragma unroll
    for (int nt = 0; nt < 16; ++nt) {
        const int col = nt * 8 + 2 * tg;
        *(float2*)&out[grow0 * HDIM + col] = make_float2(o[nt][0] * inv0, o[nt][1] * inv0);
        *(float2*)&out[grow1 * HDIM + col] = make_float2(o[nt][2] * inv1, o[nt][3] * inv1);
    }
}

// ---------------------------------------------------------------------
extern "C" void kernel_launch(void* const* d_in, const int* in_sizes, int n_in,
                              void* d_out, int out_size)
{
    (void)in_sizes; (void)n_in; (void)out_size;
    const float* x  = (const float*)d_in[0];
    const float* Wq = (const float*)d_in[1];
    const float* Wk = (const float*)d_in[2];
    const float* Wv = (const float*)d_in[3];
    float* out = (float*)d_out;

    xconv_kernel<<<(BT * CDIM) / (256 * 8), 256>>>(x);
    wconv_kernel<<<dim3(CDIM / 32, HDIM / 32, 3), dim3(32, 8)>>>(Wq, Wk, Wv);

    cudaFuncSetAttribute(qkv16_kernel,
                         cudaFuncAttributeMaxDynamicSharedMemorySize, QKV_SMEM);
    qkv16_kernel<<<(BT / 128) * 3, 256, QKV_SMEM>>>();

    cudaFuncSetAttribute(attn16_kernel,
                         cudaFuncAttributeMaxDynamicSharedMemorySize, ATTN_SMEM);
    attn16_kernel<<<256, 128, ATTN_SMEM>>>(out);
}